// round 5
// baseline (speedup 1.0000x reference)
#include <cuda_runtime.h>

// Guided attention loss: out = sum_{b,i,j} aln[b,i,j] * w(b,i,j) / B
// w = 1 - exp(-(i - j*To/Ti)^2 / (2*0.4^2)), zero for i>=To or j>=Ti.
//
// loss = sum_valid(a) - sum_band(a * exp(...)):  w == 1.0f exactly (fp32)
// outside |i - j*To/Ti| <= 2.4, so the bulk is a pure masked streaming sum.
//
// Work decomposition (R5: load balance): 32000 uniform quads (4 consecutive
// rows of one batch), grid-strided over 1776 persistent blocks -> per-block
// work variance ~7% instead of the 33% straggler of the block-per-i layout.
// Band correction = separate grid-stride pass over rows (<=5 exps per row).

#define B_DIM   64
#define T_OUT   2000
#define T_IN    512
#define NROWS   (B_DIM * T_OUT)        // 128000
#define NQUADS  (B_DIM * (T_OUT / 4))  // 32000, 500 quads per batch
#define GRID    1776                   // 148 SMs * 12
#define NEG_INV2S2 (-3.125f)
#define BAND    3.0f

__device__ double       g_acc;   // zero at load; last block resets each call
__device__ unsigned int g_cnt;

__global__ __launch_bounds__(128) void gal_main(
    const float4* __restrict__ aln,
    const int*    __restrict__ ilen,
    const int*    __restrict__ olen,
    float*        __restrict__ out)
{
    __shared__ int   siTo[B_DIM], siTi[B_DIM];
    __shared__ float sR[B_DIM], sInvR[B_DIM];

    const int t = threadIdx.x;             // 0..127
    if (t < B_DIM)          siTo[t]         = olen[t];
    else if (t < 2 * B_DIM) siTi[t - B_DIM] = ilen[t - B_DIM];
    __syncthreads();
    if (t < B_DIM) {
        const float To = (float)siTo[t], Ti = (float)siTi[t];
        sR[t]    = __fdividef(To, Ti);
        sInvR[t] = __fdividef(Ti, To);
    }
    __syncthreads();

    float acc = 0.0f;

    // ---- band pass: -sum a*exp(...) over |i - j*r| <= BAND, one row/thread ----
    {
        const int gtid = blockIdx.x * 128 + t;
        const int nth  = GRID * 128;
        for (int n = gtid; n < NROWS; n += nth) {
            const int b = n & (B_DIM - 1);
            const int i = n >> 6;
            const int To = siTo[b];
            if (i >= To) continue;
            const int   Ti   = siTi[b];
            const float fi   = (float)i;
            const float r    = sR[b];
            const float invr = sInvR[b];
            int jlo = (int)ceilf((fi - BAND) * invr);
            if (jlo < 0) jlo = 0;
            int jhi = (int)floorf((fi + BAND) * invr);
            if (jhi > Ti - 1) jhi = Ti - 1;
            const float* row = (const float*)aln + ((size_t)b * T_OUT + i) * T_IN;

            float av[5];
            #pragma unroll
            for (int u = 0; u < 5; ++u) {
                const int j = jlo + u;
                av[u] = (j <= jhi) ? __ldg(row + j) : 0.0f;
            }
            #pragma unroll
            for (int u = 0; u < 5; ++u) {
                const float d = fi - (float)(jlo + u) * r;
                acc -= av[u] * __expf(d * d * NEG_INV2S2);
            }
            for (int j = jlo + 5; j <= jhi; ++j) {   // safety; never runs here
                const float d = fi - (float)j * r;
                acc -= __ldg(row + j) * __expf(d * d * NEG_INV2S2);
            }
        }
    }

    // ---- main masked streaming sum: quads of 4 rows, same batch ----
    const int jb4 = t * 4;
    #pragma unroll 1
    for (unsigned q = blockIdx.x; q < NQUADS; q += GRID) {
        const unsigned b  = q / 500u;              // magic-mul divide
        const unsigned i0 = (q - b * 500u) * 4u;
        const int m = siTi[b] - jb4;               // valid elems in my chunk
        if (m <= 0) continue;                      // chunk dead for all 4 rows
        const int To = siTo[b];

        const float4* p = aln + ((size_t)b * T_OUT + i0) * (T_IN / 4) + t;
        float4 a[4];
        bool   rv[4];
        #pragma unroll
        for (int k = 0; k < 4; ++k) {              // front-batched, MLP=4
            rv[k] = (int)(i0 + k) < To;
            a[k] = make_float4(0.f, 0.f, 0.f, 0.f);
            if (rv[k]) a[k] = __ldcs(p + k * (T_IN / 4));
        }
        if (m >= 4) {
            #pragma unroll
            for (int k = 0; k < 4; ++k)
                acc += (a[k].x + a[k].y) + (a[k].z + a[k].w);
        } else {                                   // boundary chunk: 1 thread/row
            #pragma unroll
            for (int k = 0; k < 4; ++k) {
                acc += a[k].x;
                if (m > 1) acc += a[k].y;
                if (m > 2) acc += a[k].z;
            }
        }
    }

    // ---- block reduce + fused finalize ----
    #pragma unroll
    for (int off = 16; off > 0; off >>= 1)
        acc += __shfl_down_sync(0xFFFFFFFFu, acc, off);

    __shared__ float ws[4];
    if ((t & 31) == 0) ws[t >> 5] = acc;
    __syncthreads();

    if (t == 0) {
        atomicAdd(&g_acc, (double)(ws[0] + ws[1] + ws[2] + ws[3]));
        __threadfence();
        const unsigned done = atomicAdd(&g_cnt, 1u);
        if (done == (unsigned)(gridDim.x - 1)) {
            const double total = *((volatile double*)&g_acc);
            out[0] = (float)(total / (double)B_DIM);
            *((volatile double*)&g_acc) = 0.0;     // reset for next replay
            __threadfence();
            *((volatile unsigned*)&g_cnt) = 0u;
        }
    }
}

extern "C" void kernel_launch(void* const* d_in, const int* in_sizes, int n_in,
                              void* d_out, int out_size)
{
    const float4* aln  = (const float4*)d_in[0];
    const int*    ilen = (const int*)d_in[1];
    const int*    olen = (const int*)d_in[2];

    gal_main<<<GRID, 128>>>(aln, ilen, olen, (float*)d_out);
}